// round 4
// baseline (speedup 1.0000x reference)
#include <cuda_runtime.h>
#include <cuda_bf16.h>
#include <cstdint>

// FirstSpikeDetector: out[b][t] = 1 iff spike_train[b][t] is the first nonzero
// in row b, else 0. Input values are exact 0.0f / 1.0f.
//
// R4: back to R1's proven order (scan -> resolve ballot -> store); the R2/R3
// "zeros-before-ballot" burst was the regression. New in R4:
//  - exact single-wave grid: 1024 blocks x 8 warps = 8192 warps, each warp
//    owns 2 adjacent rows (contiguous 16KB store footprint, no wave tail);
//  - both rows' chunk-0 loads issued back-to-back (2x load MLP) before the
//    first ballot;
//  - branch-free zero store loop (16 x STG.128/lane, no one-hot compares),
//    then the electing lane overwrites one scalar with 1.0f. Common path:
//    vector `src` was zero-stored by lane `src` itself -> same-thread
//    same-address ordering, no fence needed. Rare path uses __syncwarp()
//    (warp-scope memory fence) before the cross-lane overwrite.

static constexpr int T  = 2048;   // time steps per row
static constexpr int TV = T / 4;  // float4s per row (512)

__device__ __forceinline__ void resolve_and_store(
    const float4* __restrict__ row_in,
    float4* __restrict__ row_out,
    float4 v, unsigned m, int lane)
{
    const float4 z = make_float4(0.0f, 0.0f, 0.0f, 0.0f);
    float* const row_out_f = reinterpret_cast<float*>(row_out);

    // Branch-free zero fill of the whole row: 16 x STG.128 per lane.
    #pragma unroll
    for (int i = lane; i < TV; i += 32) {
        row_out[i] = z;
    }

    if (m != 0u) {
        // Common path: first spike within elements 0..127 (vectors 0..31).
        const int src = __ffs(m) - 1;
        if (lane == src) {
            int sub;
            if      (v.x != 0.0f) sub = 0;
            else if (v.y != 0.0f) sub = 1;
            else if (v.z != 0.0f) sub = 2;
            else                  sub = 3;
            // Vector `src` was zero-stored above by THIS lane (i == lane == src
            // at the first loop iteration), so this overwrite is ordered.
            row_out_f[(src << 2) + sub] = 1.0f;
        }
    } else {
        // Rare path (P ~ 1.4e-6 per row): keep scanning chunks of 128.
        int first = -1;
        #pragma unroll 1
        for (int base = 128; base < T; base += 128) {
            float4 u = row_in[(base >> 2) + lane];
            bool a2 = (u.x != 0.0f) | (u.y != 0.0f) | (u.z != 0.0f) | (u.w != 0.0f);
            unsigned m2 = __ballot_sync(0xffffffffu, a2);
            if (m2) {
                int s2 = __ffs(m2) - 1;
                if (lane == s2) {
                    int sub;
                    if      (u.x != 0.0f) sub = 0;
                    else if (u.y != 0.0f) sub = 1;
                    else if (u.z != 0.0f) sub = 2;
                    else                  sub = 3;
                    first = base + (s2 << 2) + sub;
                }
                break;   // m2 is warp-uniform; all lanes exit together
            }
        }
        __syncwarp();   // fence: zero stores (any lane) before the overwrite
        if (first >= 0) {
            row_out_f[first] = 1.0f;
        }
    }
}

__global__ void __launch_bounds__(256)
first_spike_kernel(const float* __restrict__ in, float* __restrict__ out, int rows)
{
    const int gtid = blockIdx.x * blockDim.x + threadIdx.x;
    const int warp = gtid >> 5;
    const int lane = gtid & 31;

    const int r0 = warp * 2;
    const int r1 = r0 + 1;
    if (r0 >= rows) return;

    const float4* __restrict__ in4  = reinterpret_cast<const float4*>(in);
    float4* __restrict__       out4 = reinterpret_cast<float4*>(out);

    const float4* row_in0  = in4  + (size_t)r0 * TV;
    float4*       row_out0 = out4 + (size_t)r0 * TV;

    const bool has_r1 = (r1 < rows);
    const float4* row_in1  = in4  + (size_t)(has_r1 ? r1 : r0) * TV;
    float4*       row_out1 = out4 + (size_t)(has_r1 ? r1 : r0) * TV;

    // Issue both rows' chunk-0 loads back-to-back (2x MLP).
    float4 v0 = row_in0[lane];
    float4 v1 = row_in1[lane];

    const bool a0 = (v0.x != 0.0f) | (v0.y != 0.0f) | (v0.z != 0.0f) | (v0.w != 0.0f);
    const bool a1 = (v1.x != 0.0f) | (v1.y != 0.0f) | (v1.z != 0.0f) | (v1.w != 0.0f);
    const unsigned m0 = __ballot_sync(0xffffffffu, a0);
    const unsigned m1 = __ballot_sync(0xffffffffu, a1);

    resolve_and_store(row_in0, row_out0, v0, m0, lane);
    if (has_r1) {
        resolve_and_store(row_in1, row_out1, v1, m1, lane);
    }
}

extern "C" void kernel_launch(void* const* d_in, const int* in_sizes, int n_in,
                              void* d_out, int out_size)
{
    const float* in = (const float*)d_in[0];
    float* out = (float*)d_out;

    const int rows = in_sizes[0] / T;                     // 16384
    const int warps_needed = (rows + 1) / 2;              // 8192 (2 rows/warp)
    const int threads = 256;                              // 8 warps/block
    const int blocks  = (warps_needed * 32 + threads - 1) / threads;  // 1024

    first_spike_kernel<<<blocks, threads>>>(in, out, rows);
}

// round 5
// speedup vs baseline: 1.0779x; 1.0779x over previous
#include <cuda_runtime.h>
#include <cuda_bf16.h>
#include <cstdint>

// FirstSpikeDetector: out[b][t] = 1 iff spike_train[b][t] is the first nonzero
// in row b, else 0. Input values are exact 0.0f / 1.0f.
//
// R5 = R1's launch shape (the only one that performed: 2048 blocks x 256 thr,
// ONE row per warp, scan -> resolve -> store) + R4's lean branch-free store
// path (16 pure STG.128 zeros per lane, no per-iteration one-hot compares,
// then a single scalar overwrite by the electing lane).
//
// Post-mortems R2-R4: .cs hints, zeros-before-ballot bursts, persistent grids,
// and 2-rows/warp pairing ALL regressed. This kernel touches only the ALU fat
// in R1's store loop (alu was 9.9% there, 1.9% with the branch-free loop).

static constexpr int T  = 2048;   // time steps per row
static constexpr int TV = T / 4;  // float4s per row (512)

__global__ void __launch_bounds__(256)
first_spike_kernel(const float* __restrict__ in, float* __restrict__ out, int rows)
{
    const int gtid = blockIdx.x * blockDim.x + threadIdx.x;
    const int warp = gtid >> 5;
    const int lane = gtid & 31;
    if (warp >= rows) return;

    const float4* __restrict__ row_in  =
        reinterpret_cast<const float4*>(in)  + (size_t)warp * TV;
    float4* __restrict__ row_out =
        reinterpret_cast<float4*>(out) + (size_t)warp * TV;
    float* const row_out_f = reinterpret_cast<float*>(row_out);

    // ---- scan chunk 0 (elements 0..127) and resolve ----
    float4 v = row_in[lane];
    const bool any = (v.x != 0.0f) | (v.y != 0.0f) | (v.z != 0.0f) | (v.w != 0.0f);
    const unsigned m = __ballot_sync(0xffffffffu, any);

    // ---- branch-free zero fill: 16 x STG.128 per lane ----
    const float4 z = make_float4(0.0f, 0.0f, 0.0f, 0.0f);
    #pragma unroll
    for (int i = lane; i < TV; i += 32) {
        row_out[i] = z;
    }

    if (m != 0u) {
        // Common path (P ~ 1 - 1.4e-6): first spike within elements 0..127.
        const int src = __ffs(m) - 1;
        if (lane == src) {
            int sub;
            if      (v.x != 0.0f) sub = 0;
            else if (v.y != 0.0f) sub = 1;
            else if (v.z != 0.0f) sub = 2;
            else                  sub = 3;
            // Vector `src` was zero-stored above by THIS lane (loop iter 0,
            // i == lane == src): same-thread same-address ordering, no fence.
            row_out_f[(src << 2) + sub] = 1.0f;
        }
    } else {
        // Rare path: keep scanning chunks of 128 elements.
        int first = -1;
        #pragma unroll 1
        for (int base = 128; base < T; base += 128) {
            float4 u = row_in[(base >> 2) + lane];
            bool a2 = (u.x != 0.0f) | (u.y != 0.0f) | (u.z != 0.0f) | (u.w != 0.0f);
            unsigned m2 = __ballot_sync(0xffffffffu, a2);
            if (m2) {
                int s2 = __ffs(m2) - 1;
                if (lane == s2) {
                    int sub;
                    if      (u.x != 0.0f) sub = 0;
                    else if (u.y != 0.0f) sub = 1;
                    else if (u.z != 0.0f) sub = 2;
                    else                  sub = 3;
                    first = base + (s2 << 2) + sub;
                }
                break;   // m2 is warp-uniform; all lanes exit together
            }
        }
        __syncwarp();   // order cross-lane zero stores before the overwrite
        if (first >= 0) {
            row_out_f[first] = 1.0f;
        }
    }
}

extern "C" void kernel_launch(void* const* d_in, const int* in_sizes, int n_in,
                              void* d_out, int out_size)
{
    const float* in = (const float*)d_in[0];
    float* out = (float*)d_out;

    const int rows = in_sizes[0] / T;                       // 16384
    const int threads = 256;                                // 8 warps/block
    const int blocks = (rows * 32 + threads - 1) / threads; // 2048

    first_spike_kernel<<<blocks, threads>>>(in, out, rows);
}

// round 6
// speedup vs baseline: 1.0935x; 1.0145x over previous
#include <cuda_runtime.h>
#include <cuda_bf16.h>
#include <cstdint>

// FirstSpikeDetector: out[b][t] = 1 iff spike_train[b][t] is the first nonzero
// in row b, else 0. Input values are exact 0.0f / 1.0f.
//
// R6: R1's proven launch shape (2048 blocks x 256 thr, ONE row per warp,
// scan -> resolve -> store-with-injection) but the row fill now uses
// 256-bit stores (st.global.v8.f32 -> STG.E.256, Blackwell sm_100+):
// 8 store instructions per lane instead of 16. All profiles R1-R5 showed
// l1tex as the hottest unit (56-62%) -> the binder is store instruction /
// wavefront processing, not bytes. Halving store instructions attacks that.
//
// Scan covers the first 256 elements (2x LDG.128 per lane, P(no spike) ~ 2e-12).
// The one-hot 1.0f is injected directly into the store data (branch-free
// compares), so each output location is written exactly once -> no ordering
// hazards on the common path.

static constexpr int T   = 2048;     // time steps per row
static constexpr int TV4 = T / 4;    // float4s per row (512)

__device__ __forceinline__ void stg256(float* p,
                                       float r0, float r1, float r2, float r3,
                                       float r4, float r5, float r6, float r7)
{
    asm volatile(
        "st.global.v8.f32 [%0], {%1, %2, %3, %4, %5, %6, %7, %8};"
        :: "l"(p), "f"(r0), "f"(r1), "f"(r2), "f"(r3),
                   "f"(r4), "f"(r5), "f"(r6), "f"(r7)
        : "memory");
}

__global__ void __launch_bounds__(256)
first_spike_kernel(const float* __restrict__ in, float* __restrict__ out, int rows)
{
    const int gtid = blockIdx.x * blockDim.x + threadIdx.x;
    const int warp = gtid >> 5;
    const int lane = gtid & 31;
    if (warp >= rows) return;

    const float4* __restrict__ row_in4 =
        reinterpret_cast<const float4*>(in) + (size_t)warp * TV4;
    float* __restrict__ row_out = out + (size_t)warp * T;

    // ---- scan elements 0..255: lane covers floats [lane*8, lane*8+8) ----
    float4 a = row_in4[2 * lane];
    float4 b = row_in4[2 * lane + 1];
    const bool any = (a.x != 0.0f) | (a.y != 0.0f) | (a.z != 0.0f) | (a.w != 0.0f) |
                     (b.x != 0.0f) | (b.y != 0.0f) | (b.z != 0.0f) | (b.w != 0.0f);
    const unsigned m = __ballot_sync(0xffffffffu, any);

    int f = -1;                      // warp-uniform first-spike float index
    if (m != 0u) {
        const int src = __ffs(m) - 1;
        int sub = 0;
        if      (a.x != 0.0f) sub = 0;
        else if (a.y != 0.0f) sub = 1;
        else if (a.z != 0.0f) sub = 2;
        else if (a.w != 0.0f) sub = 3;
        else if (b.x != 0.0f) sub = 4;
        else if (b.y != 0.0f) sub = 5;
        else if (b.z != 0.0f) sub = 6;
        else                  sub = 7;
        sub = __shfl_sync(0xffffffffu, sub, src);
        f = (src << 3) + sub;
    }

    // ---- row fill: 8 x STG.256 per lane, one-hot injected branch-free ----
    const int lane8 = lane << 3;     // this lane's slot-0 float index at i=0
    #pragma unroll
    for (int i = 0; i < 8; i++) {
        const int base = i * 256 + lane8;   // float index of this v8's slot 0
        stg256(row_out + base,
               (base + 0 == f) ? 1.0f : 0.0f,
               (base + 1 == f) ? 1.0f : 0.0f,
               (base + 2 == f) ? 1.0f : 0.0f,
               (base + 3 == f) ? 1.0f : 0.0f,
               (base + 4 == f) ? 1.0f : 0.0f,
               (base + 5 == f) ? 1.0f : 0.0f,
               (base + 6 == f) ? 1.0f : 0.0f,
               (base + 7 == f) ? 1.0f : 0.0f);
    }

    if (m == 0u) {
        // Rare path (P ~ 2e-12 per row): scan elements 256.. in 128-chunks.
        int first = -1;
        #pragma unroll 1
        for (int base = 256; base < T; base += 128) {
            float4 u = row_in4[(base >> 2) + lane];
            bool a2 = (u.x != 0.0f) | (u.y != 0.0f) | (u.z != 0.0f) | (u.w != 0.0f);
            unsigned m2 = __ballot_sync(0xffffffffu, a2);
            if (m2) {
                int s2 = __ffs(m2) - 1;
                if (lane == s2) {
                    int sub;
                    if      (u.x != 0.0f) sub = 0;
                    else if (u.y != 0.0f) sub = 1;
                    else if (u.z != 0.0f) sub = 2;
                    else                  sub = 3;
                    first = base + (s2 << 2) + sub;
                }
                break;   // m2 is warp-uniform; all lanes exit together
            }
        }
        __syncwarp();    // order the zero stores before the cross-lane overwrite
        if (first >= 0) {
            row_out[first] = 1.0f;
        }
    }
}

extern "C" void kernel_launch(void* const* d_in, const int* in_sizes, int n_in,
                              void* d_out, int out_size)
{
    const float* in = (const float*)d_in[0];
    float* out = (float*)d_out;

    const int rows = in_sizes[0] / T;                       // 16384
    const int threads = 256;                                // 8 warps/block
    const int blocks = (rows * 32 + threads - 1) / threads; // 2048

    first_spike_kernel<<<blocks, threads>>>(in, out, rows);
}

// round 7
// speedup vs baseline: 1.1580x; 1.0590x over previous
#include <cuda_runtime.h>
#include <cuda_bf16.h>
#include <cstdint>

// FirstSpikeDetector: out[b][t] = 1 iff spike_train[b][t] is the first nonzero
// in row b, else 0. Input values are exact 0.0f / 1.0f.
//
// R7: split producer experiment.
//   Node 1: cudaMemsetAsync(d_out, 0, 128MB)  -- driver fill path writes the
//           zeros (no SM/L1tex involvement, best-case write stream).
//   Node 2: detector kernel -- one warp per row, reads the first 128 elements
//           (~8MB total), ballot-elects the first spike, writes ONE float.
//           Rare path (P ~ 1.4e-6/row): continue scanning in 128-chunks.
// Both are graph-capturable (memset node + kernel node), allocation-free,
// and ordered by the stream: memset completes before the 1.0f stores.
//
// R1-R6 established that SM-side zero-writing is pinned at ~27.3us bench no
// matter the instruction mix; this tests whether the copy-engine/fill path
// sustains a higher write rate than our STG stream.

static constexpr int T   = 2048;    // time steps per row
static constexpr int TV4 = T / 4;   // float4s per row (512)

__global__ void __launch_bounds__(256)
first_spike_detect(const float* __restrict__ in, float* __restrict__ out, int rows)
{
    const int gtid = blockIdx.x * blockDim.x + threadIdx.x;
    const int warp = gtid >> 5;
    const int lane = gtid & 31;
    if (warp >= rows) return;

    const float4* __restrict__ row_in =
        reinterpret_cast<const float4*>(in) + (size_t)warp * TV4;
    float* __restrict__ row_out = out + (size_t)warp * T;

    // ---- scan elements 0..127 (1 x LDG.128 per lane) ----
    float4 v = row_in[lane];
    const bool any = (v.x != 0.0f) | (v.y != 0.0f) | (v.z != 0.0f) | (v.w != 0.0f);
    const unsigned m = __ballot_sync(0xffffffffu, any);

    if (m != 0u) {
        // Common path: first spike within elements 0..127.
        const int src = __ffs(m) - 1;
        if (lane == src) {
            int sub;
            if      (v.x != 0.0f) sub = 0;
            else if (v.y != 0.0f) sub = 1;
            else if (v.z != 0.0f) sub = 2;
            else                  sub = 3;
            row_out[(src << 2) + sub] = 1.0f;   // zeros already laid by memset
        }
        return;
    }

    // Rare path (P ~ 1.4e-6 per row): keep scanning chunks of 128 elements.
    #pragma unroll 1
    for (int base = 128; base < T; base += 128) {
        float4 u = row_in[(base >> 2) + lane];
        bool a2 = (u.x != 0.0f) | (u.y != 0.0f) | (u.z != 0.0f) | (u.w != 0.0f);
        unsigned m2 = __ballot_sync(0xffffffffu, a2);
        if (m2) {
            int s2 = __ffs(m2) - 1;
            if (lane == s2) {
                int sub;
                if      (u.x != 0.0f) sub = 0;
                else if (u.y != 0.0f) sub = 1;
                else if (u.z != 0.0f) sub = 2;
                else                  sub = 3;
                row_out[base + (s2 << 2) + sub] = 1.0f;
            }
            return;   // m2 is warp-uniform; all lanes exit together
        }
    }
    // No spike anywhere in the row: memset zeros are the correct output.
}

extern "C" void kernel_launch(void* const* d_in, const int* in_sizes, int n_in,
                              void* d_out, int out_size)
{
    const float* in = (const float*)d_in[0];
    float* out = (float*)d_out;

    const int rows = in_sizes[0] / T;                       // 16384

    // Node 1: bulk zero fill via the driver's fill path (memset graph node).
    cudaMemsetAsync(d_out, 0, (size_t)out_size * sizeof(float), 0);

    // Node 2: sparse detector (reads ~8MB, writes 64KB).
    const int threads = 256;                                // 8 warps/block
    const int blocks  = (rows * 32 + threads - 1) / threads; // 2048
    first_spike_detect<<<blocks, threads>>>(in, out, rows);
}